// round 1
// baseline (speedup 1.0000x reference)
#include <cuda_runtime.h>
#include <math.h>

typedef unsigned long long u64;

#define B_DIM 8
#define H_DIM 16
#define N_PTS 1024

__device__ float g_sde[B_DIM * H_DIM];

__device__ __forceinline__ u64 pk2(float lo, float hi) {
    u64 r; asm("mov.b64 %0, {%1,%2};" : "=l"(r) : "f"(lo), "f"(hi)); return r;
}
__device__ __forceinline__ u64 ffma2(u64 a, u64 b, u64 c) {
    u64 d; asm("fma.rn.f32x2 %0, %1, %2, %3;" : "=l"(d) : "l"(a), "l"(b), "l"(c)); return d;
}
__device__ __forceinline__ void unpk2(u64 v, float& lo, float& hi) {
    asm("mov.b64 {%0,%1}, %2;" : "=f"(lo), "=f"(hi) : "l"(v));
}

// One block per (b,h). 512 threads, each owns rows i=t and i=t+512.
// sde[b,h] = 2 * mean_i min_j |refl_i - s_j|^2   (reflection-isometry identity
// collapses the two chamfer directions into one).
__global__ void __launch_bounds__(512, 1)
chamfer_kernel(const float* __restrict__ y_pred, const float* __restrict__ sp)
{
    const int bh = blockIdx.x;
    const int b  = bh >> 4;           // H_DIM = 16
    const int t  = threadIdx.x;

    // plane params (all threads compute redundantly)
    const float* yp = y_pred + 4 * bh;
    float nx = yp[0], ny = yp[1], nz = yp[2], pd = yp[3];
    float inv = 1.0f / sqrtf(nx * nx + ny * ny + nz * nz);
    nx *= inv; ny *= inv; nz *= inv;

    __shared__ ulonglong2 shA[512];   // {x0,x1, y0,y1} packed pairs of points
    __shared__ ulonglong2 shB[512];   // {z0,z1, ss0,ss1}
    __shared__ float red[512];

    const float* pb = sp + b * (N_PTS * 3);

    // ---- build packed point table: thread t handles points 2t, 2t+1 ----
    {
        const float2* pb2 = (const float2*)pb;      // 3072 floats, 8B aligned
        float2 q0 = pb2[3 * t + 0];
        float2 q1 = pb2[3 * t + 1];
        float2 q2 = pb2[3 * t + 2];
        float x0 = q0.x, y0 = q0.y, z0 = q1.x;
        float x1 = q1.y, y1 = q2.x, z1 = q2.y;
        float s0 = fmaf(x0, x0, fmaf(y0, y0, z0 * z0));
        float s1 = fmaf(x1, x1, fmaf(y1, y1, z1 * z1));
        float4 va; va.x = x0; va.y = x1; va.z = y0; va.w = y1;
        float4 vb; vb.x = z0; vb.y = z1; vb.z = s0; vb.w = s1;
        ((float4*)shA)[t] = va;
        ((float4*)shB)[t] = vb;
    }

    // ---- per-thread rows: reflect points i0=t, i1=t+512 across the plane ----
    float sxa = pb[3 * t + 0], sya = pb[3 * t + 1], sza = pb[3 * t + 2];
    const int i1 = t + 512;
    float sxb = pb[3 * i1 + 0], syb = pb[3 * i1 + 1], szb = pb[3 * i1 + 2];

    float p0 = fmaf(nx, sxa, fmaf(ny, sya, fmaf(nz, sza, pd)));
    float rx0 = fmaf(-2.0f * p0, nx, sxa);
    float ry0 = fmaf(-2.0f * p0, ny, sya);
    float rz0 = fmaf(-2.0f * p0, nz, sza);
    float rr0 = fmaf(rx0, rx0, fmaf(ry0, ry0, rz0 * rz0));

    float p1 = fmaf(nx, sxb, fmaf(ny, syb, fmaf(nz, szb, pd)));
    float rx1 = fmaf(-2.0f * p1, nx, sxb);
    float ry1 = fmaf(-2.0f * p1, ny, syb);
    float rz1 = fmaf(-2.0f * p1, nz, szb);
    float rr1 = fmaf(rx1, rx1, fmaf(ry1, ry1, rz1 * rz1));

    // packed (-2*refl) broadcast constants
    u64 ax0 = pk2(-2.0f * rx0, -2.0f * rx0);
    u64 ay0 = pk2(-2.0f * ry0, -2.0f * ry0);
    u64 az0 = pk2(-2.0f * rz0, -2.0f * rz0);
    u64 ax1 = pk2(-2.0f * rx1, -2.0f * rx1);
    u64 ay1 = pk2(-2.0f * ry1, -2.0f * ry1);
    u64 az1 = pk2(-2.0f * rz1, -2.0f * rz1);

    __syncthreads();

    const float INF = __int_as_float(0x7f800000);
    float m00 = INF, m01 = INF, m10 = INF, m11 = INF;

    // inner loop: 512 packed j-pairs, 4 pair-distances per iter
    #pragma unroll 8
    for (int j = 0; j < 512; ++j) {
        ulonglong2 A  = shA[j];   // A.x={x0,x1}  A.y={y0,y1}
        ulonglong2 Bv = shB[j];   // Bv.x={z0,z1} Bv.y={ss0,ss1}

        u64 v = ffma2(az0, Bv.x, Bv.y);
        v = ffma2(ay0, A.y, v);
        v = ffma2(ax0, A.x, v);
        float vl, vh; unpk2(v, vl, vh);
        m00 = fminf(m00, vl); m01 = fminf(m01, vh);

        u64 w = ffma2(az1, Bv.x, Bv.y);
        w = ffma2(ay1, A.y, w);
        w = ffma2(ax1, A.x, w);
        float wl, wh; unpk2(w, wl, wh);
        m10 = fminf(m10, wl); m11 = fminf(m11, wh);
    }

    float local = (rr0 + fminf(m00, m01)) + (rr1 + fminf(m10, m11));

    // deterministic block reduce
    red[t] = local;
    __syncthreads();
    if (t < 256) red[t] += red[t + 256];
    __syncthreads();
    if (t < 128) red[t] += red[t + 128];
    __syncthreads();
    if (t < 64)  red[t] += red[t + 64];
    __syncthreads();
    if (t < 32) {
        float v = red[t] + red[t + 32];
        v += __shfl_down_sync(0xffffffffu, v, 16);
        v += __shfl_down_sync(0xffffffffu, v, 8);
        v += __shfl_down_sync(0xffffffffu, v, 4);
        v += __shfl_down_sync(0xffffffffu, v, 2);
        v += __shfl_down_sync(0xffffffffu, v, 1);
        if (t == 0) g_sde[bh] = 2.0f * (v * (1.0f / 1024.0f));
    }
}

// One block per b: centroid, conf, angle-based suppression, stable sort, scatter.
__global__ void __launch_bounds__(256, 1)
epilogue_kernel(const float* __restrict__ y_pred, const float* __restrict__ sp,
                float* __restrict__ out)
{
    const int b = blockIdx.x;
    const int t = threadIdx.x;

    __shared__ float rxs[256], rys[256], rzs[256];
    __shared__ float cmx, cmy, cmz;
    __shared__ float snx[16], sny[16], snz[16], ssd[16], skey[16];

    // centroid of sample_points[b]
    const float* pb = sp + b * (N_PTS * 3);
    float ax = 0.f, ay = 0.f, az = 0.f;
    for (int i = t; i < N_PTS; i += 256) {
        ax += pb[3 * i + 0]; ay += pb[3 * i + 1]; az += pb[3 * i + 2];
    }
    rxs[t] = ax; rys[t] = ay; rzs[t] = az;
    __syncthreads();
    for (int s = 128; s > 0; s >>= 1) {
        if (t < s) { rxs[t] += rxs[t + s]; rys[t] += rys[t + s]; rzs[t] += rzs[t + s]; }
        __syncthreads();
    }
    if (t == 0) {
        cmx = rxs[0] * (1.0f / N_PTS);
        cmy = rys[0] * (1.0f / N_PTS);
        cmz = rzs[0] * (1.0f / N_PTS);
    }

    float nx = 0, ny = 0, nz = 0, pd = 0, sde = 0, conf = 0;
    bool keep = false;

    if (t < H_DIM) {
        const float* yp = y_pred + 4 * (b * H_DIM + t);
        nx = yp[0]; ny = yp[1]; nz = yp[2]; pd = yp[3];
        float inv = 1.0f / sqrtf(nx * nx + ny * ny + nz * nz);
        nx *= inv; ny *= inv; nz *= inv;
        sde = g_sde[b * H_DIM + t];
        snx[t] = nx; sny[t] = ny; snz[t] = nz; ssd[t] = sde;
    }
    __syncthreads();

    if (t < H_DIM) {
        float mn = ssd[0], mx = ssd[0];
        #pragma unroll
        for (int g = 1; g < H_DIM; ++g) { mn = fminf(mn, ssd[g]); mx = fmaxf(mx, ssd[g]); }
        conf = 1.0f - (sde - mn) / fabsf(mx - mn);

        bool valid = (sde <= 10.0f);
        bool any = false;
        #pragma unroll
        for (int g = 0; g < H_DIM; ++g) {
            if (g == t) continue;
            float c = nx * snx[g] + ny * sny[g] + nz * snz[g];
            c = fminf(1.0f, fmaxf(-1.0f, c));
            float ang = acosf(c) * 57.29577951308232f;
            bool close = (ang < 30.0f) || ((180.0f - ang) < 30.0f);
            if (close && (ssd[g] <= 10.0f) && (sde >= ssd[g])) any = true;
        }
        keep = valid && !any;
        skey[t] = keep ? conf : __int_as_float(0xff800000);  // -inf
    }
    __syncthreads();

    if (t < H_DIM) {
        float key = skey[t];
        int rank = 0;
        #pragma unroll
        for (int g = 0; g < H_DIM; ++g) {
            float kg = skey[g];
            if (kg > key || (kg == key && g < t)) rank++;
        }
        float* o = out + (b * H_DIM + rank) * 8;
        if (keep) {
            float pj = fmaf(nx, cmx, fmaf(ny, cmy, fmaf(nz, cmz, pd)));
            o[0] = nx; o[1] = ny; o[2] = nz;
            o[3] = cmx - pj * nx;
            o[4] = cmy - pj * ny;
            o[5] = cmz - pj * nz;
            o[6] = conf;
            o[7] = sde;
        } else {
            #pragma unroll
            for (int c = 0; c < 8; ++c) o[c] = 0.0f;
        }
    }
}

extern "C" void kernel_launch(void* const* d_in, const int* in_sizes, int n_in,
                              void* d_out, int out_size)
{
    const float* y_pred = (const float*)d_in[0];   // (8,16,4)
    const float* sp     = (const float*)d_in[1];   // (8,1024,3)
    float* out          = (float*)d_out;           // (8,16,8)

    chamfer_kernel<<<B_DIM * H_DIM, 512>>>(y_pred, sp);
    epilogue_kernel<<<B_DIM, 256>>>(y_pred, sp, out);
}